// round 6
// baseline (speedup 1.0000x reference)
#include <cuda_runtime.h>
#include <cuda_bf16.h>

// Problem constants
#define B_  64
#define T_  512
#define H_  768
#define S_  128
#define M_  (B_ * S_)      // 8192 rows through the MLP

// GEMM tiling
#define BM 128
#define BN 128
#define BK 16

// Scratch buffers (no allocation allowed -> __device__ globals)
__device__ __align__(128) float g_bufA[M_ * H_];   // pooled / x2
__device__ __align__(128) float g_bufB[M_ * H_];   // x1

// ---------------------------------------------------------------------------
// Kernel 1: per-(batch, statement) mean pooling.
// statements_ids are sorted per row, so segment = contiguous token range.
// One block per (b, s): binary-search the range once, then 256 threads
// accumulate 3 columns each (H=768=3*256). Writes g_bufA.
// ---------------------------------------------------------------------------
__global__ __launch_bounds__(256) void pool_kernel(const float* __restrict__ hidden,
                                                   const int*   __restrict__ sids)
{
    const int bs = blockIdx.x;            // 0 .. M_-1
    const int b  = bs >> 7;               // / S_
    const int s  = bs & (S_ - 1);

    __shared__ int s_lo, s_hi;
    if (threadIdx.x == 0) {
        const int* ids = sids + b * T_;
        int lo = 0, hi = T_;
        while (lo < hi) { int m = (lo + hi) >> 1; if (ids[m] < s) lo = m + 1; else hi = m; }
        s_lo = lo;
        hi = T_;
        while (lo < hi) { int m = (lo + hi) >> 1; if (ids[m] < s + 1) lo = m + 1; else hi = m; }
        s_hi = lo;
    }
    __syncthreads();

    const int lo  = s_lo;
    const int cnt = s_hi - s_lo;
    const float inv = 1.0f / (float)max(cnt, 1);   // matches ref: sums / max(cnt,1)

    const int c = threadIdx.x;
    float a0 = 0.f, a1 = 0.f, a2 = 0.f;
    const float* row = hidden + ((long)b * T_ + lo) * H_;
    for (int t = 0; t < cnt; ++t, row += H_) {
        a0 += row[c];
        a1 += row[c + 256];
        a2 += row[c + 512];
    }
    float* o = g_bufA + (long)bs * H_;
    o[c]       = a0 * inv;
    o[c + 256] = a1 * inv;
    o[c + 512] = a2 * inv;
}

// ---------------------------------------------------------------------------
// GEMM + bias + exact GELU.  C[M_,768] = gelu(A[M_,768] @ W[768,768] + bias)
// fp32 with packed fma.rn.f32x2 (2x FFMA throughput on sm_103a).
// 128x128x16 block tile, 256 threads, 8x8 per-thread tile (acc packed along n),
// cp.async double-buffered shared memory.
// ---------------------------------------------------------------------------
__device__ __forceinline__ float gelu_exact(float x)
{
    return 0.5f * x * (1.0f + erff(x * 0.70710678118654752f));
}

__device__ __forceinline__ void cp16(unsigned smem, const void* gmem)
{
    asm volatile("cp.async.cg.shared.global [%0], [%1], 16;\n" :: "r"(smem), "l"(gmem));
}

union F4U64 { float4 f; unsigned long long u[2]; };

// flip == 0 : A = g_bufA, C = g_bufB
// flip == 1 : A = g_bufB, C = g_bufA
__global__ __launch_bounds__(256, 2) void gemm_gelu_kernel(const float* __restrict__ W,
                                                           const float* __restrict__ bias,
                                                           int flip)
{
    const float* A = flip ? g_bufB : g_bufA;
    float*       C = flip ? g_bufA : g_bufB;

    __shared__ __align__(16) float As[2][BM][BK];   // [m][k]
    __shared__ __align__(16) float Ws[2][BK][BN];   // [k][n]

    const int t  = threadIdx.x;
    const int m0 = blockIdx.y * BM;
    const int n0 = blockIdx.x * BN;

    // cp.async loader mapping
    const int la_m = t >> 2;              // 0..63  (A: row; also row+64)
    const int la_k = (t & 3) * 4;         // k within tile, float4
    const int lw_k = t >> 5;              // 0..7   (W: k row; also k+8)
    const int lw_n = (t & 31) * 4;        // n within tile, float4

    const unsigned sA = (unsigned)__cvta_generic_to_shared(&As[0][0][0]);
    const unsigned sW = (unsigned)__cvta_generic_to_shared(&Ws[0][0][0]);

    auto issue = [&](int kt, int buf) {
        const int kb = kt * BK;
        const float* ga0 = A + (long)(m0 + la_m) * H_ + kb + la_k;
        const float* ga1 = ga0 + 64L * H_;
        unsigned da0 = sA + (unsigned)(((buf * BM + la_m) * BK + la_k) * 4);
        unsigned da1 = da0 + 64 * BK * 4;
        cp16(da0, ga0);
        cp16(da1, ga1);
        const float* gw0 = W + (long)(kb + lw_k) * H_ + n0 + lw_n;
        const float* gw1 = gw0 + 8L * H_;
        unsigned dw0 = sW + (unsigned)(((buf * BK + lw_k) * BN + lw_n) * 4);
        unsigned dw1 = dw0 + 8 * BN * 4;
        cp16(dw0, gw0);
        cp16(dw1, gw1);
        asm volatile("cp.async.commit_group;\n");
    };

    // compute mapping: 16x16 thread grid; thread tile 8 rows x 8 cols,
    // rows = {ty*4+0..3, 64+ty*4+0..3}, cols = {tx*4+0..3, 64+tx*4+0..3}
    const int tx = t & 15;
    const int ty = t >> 4;

    unsigned long long acc[8][4];   // 8 rows x 4 packed f32x2 column-pairs
#pragma unroll
    for (int i = 0; i < 8; ++i)
#pragma unroll
        for (int j = 0; j < 4; ++j) acc[i][j] = 0ull;

    issue(0, 0);

    const int KT = H_ / BK;  // 48
    for (int kt = 0; kt < KT; ++kt) {
        const int buf = kt & 1;
        if (kt + 1 < KT) {
            issue(kt + 1, buf ^ 1);
            asm volatile("cp.async.wait_group 1;\n");
        } else {
            asm volatile("cp.async.wait_group 0;\n");
        }
        __syncthreads();

#pragma unroll
        for (int kk = 0; kk < BK; ++kk) {
            float a[8];
#pragma unroll
            for (int i = 0; i < 4; ++i) {
                a[i]     = As[buf][ty * 4 + i][kk];        // broadcast LDS (2 addrs/warp)
                a[i + 4] = As[buf][64 + ty * 4 + i][kk];
            }
            F4U64 bl, bh;
            bl.f = *(const float4*)&Ws[buf][kk][tx * 4];
            bh.f = *(const float4*)&Ws[buf][kk][64 + tx * 4];
            const unsigned long long b2[4] = { bl.u[0], bl.u[1], bh.u[0], bh.u[1] };

#pragma unroll
            for (int i = 0; i < 8; ++i) {
                unsigned long long ad;
                asm("mov.b64 %0, {%1, %1};" : "=l"(ad) : "r"(__float_as_uint(a[i])));
                asm("fma.rn.f32x2 %0, %1, %2, %0;" : "+l"(acc[i][0]) : "l"(ad), "l"(b2[0]));
                asm("fma.rn.f32x2 %0, %1, %2, %0;" : "+l"(acc[i][1]) : "l"(ad), "l"(b2[1]));
                asm("fma.rn.f32x2 %0, %1, %2, %0;" : "+l"(acc[i][2]) : "l"(ad), "l"(b2[2]));
                asm("fma.rn.f32x2 %0, %1, %2, %0;" : "+l"(acc[i][3]) : "l"(ad), "l"(b2[3]));
            }
        }
        __syncthreads();
    }

    // epilogue: bias + exact GELU, vectorized stores
    const float4 bias0 = *(const float4*)&bias[n0 + tx * 4];
    const float4 bias1 = *(const float4*)&bias[n0 + 64 + tx * 4];

#pragma unroll
    for (int i = 0; i < 8; ++i) {
        const int row = m0 + ((i < 4) ? (ty * 4 + i) : (64 + ty * 4 + (i - 4)));
        float4 o0, o1;
        o0.x = gelu_exact(__uint_as_float((unsigned)(acc[i][0]      )) + bias0.x);
        o0.y = gelu_exact(__uint_as_float((unsigned)(acc[i][0] >> 32)) + bias0.y);
        o0.z = gelu_exact(__uint_as_float((unsigned)(acc[i][1]      )) + bias0.z);
        o0.w = gelu_exact(__uint_as_float((unsigned)(acc[i][1] >> 32)) + bias0.w);
        o1.x = gelu_exact(__uint_as_float((unsigned)(acc[i][2]      )) + bias1.x);
        o1.y = gelu_exact(__uint_as_float((unsigned)(acc[i][2] >> 32)) + bias1.y);
        o1.z = gelu_exact(__uint_as_float((unsigned)(acc[i][3]      )) + bias1.z);
        o1.w = gelu_exact(__uint_as_float((unsigned)(acc[i][3] >> 32)) + bias1.w);
        *(float4*)&C[(long)row * H_ + n0 + tx * 4]      = o0;
        *(float4*)&C[(long)row * H_ + n0 + 64 + tx * 4] = o1;
    }
}

// ---------------------------------------------------------------------------
// Kernel 4: out[row] = sigmoid(x2[row,:] . w3 + b3).  One warp per row.
// Reads g_bufA (x2 after the flip=1 GEMM).
// ---------------------------------------------------------------------------
__global__ __launch_bounds__(256) void head_kernel(const float* __restrict__ w3,
                                                   const float* __restrict__ b3,
                                                   float* __restrict__ out)
{
    const int row  = blockIdx.x * 8 + (threadIdx.x >> 5);
    const int lane = threadIdx.x & 31;
    const float* x = g_bufA + (long)row * H_;

    float s = 0.f;
#pragma unroll
    for (int c = lane; c < H_; c += 32) s += x[c] * w3[c];
#pragma unroll
    for (int o = 16; o > 0; o >>= 1) s += __shfl_xor_sync(0xffffffffu, s, o);

    if (lane == 0) {
        const float z = s + b3[0];
        out[row] = 1.0f / (1.0f + expf(-z));
    }
}

// ---------------------------------------------------------------------------
// Launch: pool -> gemm(w1) -> gemm(w2) -> head.  All on the default stream,
// graph-capturable (kernel launches only, no allocs, no syncs).
// ---------------------------------------------------------------------------
extern "C" void kernel_launch(void* const* d_in, const int* in_sizes, int n_in,
                              void* d_out, int out_size)
{
    const float* hidden = (const float*)d_in[0];
    const int*   sids   = (const int*)  d_in[1];
    const float* w1     = (const float*)d_in[2];
    const float* b1     = (const float*)d_in[3];
    const float* w2     = (const float*)d_in[4];
    const float* b2     = (const float*)d_in[5];
    const float* w3     = (const float*)d_in[6];
    const float* b3     = (const float*)d_in[7];
    float*       out    = (float*)d_out;

    pool_kernel<<<M_, 256>>>(hidden, sids);                 // -> g_bufA

    dim3 grid(H_ / BN, M_ / BM);                            // (6, 64)
    gemm_gelu_kernel<<<grid, 256>>>(w1, b1, /*flip=*/0);    // g_bufA -> g_bufB
    gemm_gelu_kernel<<<grid, 256>>>(w2, b2, /*flip=*/1);    // g_bufB -> g_bufA

    head_kernel<<<M_ / 8, 256>>>(w3, b3, out);              // g_bufA -> out
}

// round 11
// speedup vs baseline: 1.3619x; 1.3619x over previous
#include <cuda_runtime.h>
#include <cuda_bf16.h>
#include <cstdint>

// Problem constants
#define B_  64
#define T_  512
#define H_  768
#define S_  128
#define M_  (B_ * S_)          // 8192 rows through the MLP

// GEMM tiling (warp-level mma.sync)
#define BM 128
#define BN 128
#define BKC 32                     // bf16 K per chunk
#define KPHASES 3                  // Ahi*Bhi + Alo*Bhi + Ahi*Blo
#define CHPP (H_ / BKC)            // 24 chunks per phase
#define NCH (KPHASES * CHPP)       // 72 chunks over K_eff = 2304

// Padded, UN-swizzled smem tiles: 128 rows x (32 bf16 data + 8 pad) = 80 bytes
// Static shared: 2 stages x (A+B) = 40960 bytes (< 48KB, no attribute opt-in).
#define ROWB    80
#define TILE_B  (128 * ROWB)        // 10240
#define STAGE_B (2 * TILE_B)        // 20480
#define SMEM_B  (2 * STAGE_B)       // 40960

// Scratch (no allocation allowed -> __device__ globals).
// CRITICAL: these are referenced ONLY inside device code. Passing a __device__
// global as a kernel argument from host code passes the HOST shadow symbol's
// address; on GB300 (HMM/ATS, pageableMemoryAccess=1) that host address is
// GPU-dereferenceable, so kernels silently read zero-filled host .bss instead
// of trapping -- the exact failure mode of rounds 6-10.
__device__ __align__(128) __nv_bfloat16 g_ahi[M_ * H_];
__device__ __align__(128) __nv_bfloat16 g_alo[M_ * H_];
__device__ __align__(128) __nv_bfloat16 g_xhi[M_ * H_];
__device__ __align__(128) __nv_bfloat16 g_xlo[M_ * H_];
__device__ __align__(128) __nv_bfloat16 g_w1hi[H_ * H_];
__device__ __align__(128) __nv_bfloat16 g_w1lo[H_ * H_];
__device__ __align__(128) __nv_bfloat16 g_w2hi[H_ * H_];
__device__ __align__(128) __nv_bfloat16 g_w2lo[H_ * H_];
__device__ __align__(128) float g_x2[M_ * H_];

// ---------------------------------------------------------------------------
// Helpers
// ---------------------------------------------------------------------------
__device__ __forceinline__ void cp16(uint32_t smem, const void* gmem)
{
    asm volatile("cp.async.cg.shared.global [%0], [%1], 16;\n"
                 :: "r"(smem), "l"(gmem) : "memory");
}

__device__ __forceinline__ void mma_bf16(float* d, const uint32_t* a,
                                         uint32_t b0, uint32_t b1)
{
    asm volatile(
        "mma.sync.aligned.m16n8k16.row.col.f32.bf16.bf16.f32 "
        "{%0,%1,%2,%3}, {%4,%5,%6,%7}, {%8,%9}, {%0,%1,%2,%3};"
        : "+f"(d[0]), "+f"(d[1]), "+f"(d[2]), "+f"(d[3])
        : "r"(a[0]), "r"(a[1]), "r"(a[2]), "r"(a[3]), "r"(b0), "r"(b1));
}

__device__ __forceinline__ float gelu_exact(float x)
{
    return 0.5f * x * (1.0f + erff(x * 0.70710678118654752f));
}

__device__ __forceinline__ void split_bf16(float v, __nv_bfloat16& h, __nv_bfloat16& l)
{
    h = __float2bfloat16(v);
    l = __float2bfloat16(v - __bfloat162float(h));
}

// ---------------------------------------------------------------------------
// Kernel 1: per-(batch, statement) mean pooling -> split bf16 (g_ahi/g_alo).
// Sorted ids -> contiguous token range via binary search. One block per (b,s).
// ---------------------------------------------------------------------------
__global__ __launch_bounds__(256) void pool_kernel(const float* __restrict__ hidden,
                                                   const int*   __restrict__ sids)
{
    const int bs = blockIdx.x;
    const int b  = bs >> 7;
    const int s  = bs & (S_ - 1);

    __shared__ int s_lo, s_hi;
    if (threadIdx.x == 0) {
        const int* ids = sids + b * T_;
        int lo = 0, hi = T_;
        while (lo < hi) { int m = (lo + hi) >> 1; if (ids[m] < s) lo = m + 1; else hi = m; }
        s_lo = lo;
        hi = T_;
        while (lo < hi) { int m = (lo + hi) >> 1; if (ids[m] < s + 1) lo = m + 1; else hi = m; }
        s_hi = lo;
    }
    __syncthreads();

    const int lo  = s_lo;
    const int cnt = s_hi - s_lo;
    const float inv = 1.0f / (float)max(cnt, 1);

    const int c = threadIdx.x;
    float a0 = 0.f, a1 = 0.f, a2 = 0.f;
    const float* row = hidden + ((size_t)b * T_ + lo) * H_;
    for (int t = 0; t < cnt; ++t, row += H_) {
        a0 += row[c];
        a1 += row[c + 256];
        a2 += row[c + 512];
    }
    const size_t o = (size_t)bs * H_;
    __nv_bfloat16 h, l;
    split_bf16(a0 * inv, h, l); g_ahi[o + c]       = h; g_alo[o + c]       = l;
    split_bf16(a1 * inv, h, l); g_ahi[o + c + 256] = h; g_alo[o + c + 256] = l;
    split_bf16(a2 * inv, h, l); g_ahi[o + c + 512] = h; g_alo[o + c + 512] = l;
}

// ---------------------------------------------------------------------------
// Kernel 2: weight transpose + bf16 split.  W[k][n] -> hi/lo[n][k].
// which==0 -> g_w1hi/g_w1lo, which==1 -> g_w2hi/g_w2lo (selected in device code).
// ---------------------------------------------------------------------------
__global__ __launch_bounds__(256) void wsplit_kernel(const float* __restrict__ W,
                                                     int which)
{
    __nv_bfloat16* hi = which ? g_w2hi : g_w1hi;
    __nv_bfloat16* lo = which ? g_w2lo : g_w1lo;

    __shared__ float tile[32][33];
    const int kb = blockIdx.y * 32, nb = blockIdx.x * 32;
    const int tx = threadIdx.x, ty = threadIdx.y;   // 32 x 8

#pragma unroll
    for (int i = ty; i < 32; i += 8)
        tile[i][tx] = W[(size_t)(kb + i) * H_ + nb + tx];
    __syncthreads();
#pragma unroll
    for (int i = ty; i < 32; i += 8) {
        const float v = tile[tx][i];               // W[kb+tx][nb+i]
        const size_t o = (size_t)(nb + i) * H_ + kb + tx;
        __nv_bfloat16 h, l;
        split_bf16(v, h, l);
        hi[o] = h;
        lo[o] = l;
    }
}

// ---------------------------------------------------------------------------
// Kernel 3: bf16 mma.sync GEMM + bias + exact GELU.
// K_eff = 3*H via phases: [Ahi|Alo|Ahi] . [Bhi|Bhi|Blo] (fp32-accurate product;
// only the Alo*Blo term ~2^-16 relative is dropped).
// CTA 128x128, 8 warps of 32x64. Plain 32-bit LDS fragment loads transcribing
// the PTX m16n8k16 fragment formulas; padded 80B rows are bank-conflict-free.
// MODE 0: A=g_ahi/g_alo, B=g_w1*, out split bf16 -> g_xhi/g_xlo.
// MODE 1: A=g_xhi/g_xlo, B=g_w2*, out fp32 -> g_x2.
// All scratch buffers referenced directly (device-side symbols).
// ---------------------------------------------------------------------------
template <int MODE>
__global__ __launch_bounds__(256) void gemm_mma_kernel(const float* __restrict__ bias)
{
    const __nv_bfloat16* __restrict__ Ahi = MODE ? g_xhi : g_ahi;
    const __nv_bfloat16* __restrict__ Alo = MODE ? g_xlo : g_alo;
    const __nv_bfloat16* __restrict__ Bhi = MODE ? g_w2hi : g_w1hi;
    const __nv_bfloat16* __restrict__ Blo = MODE ? g_w2lo : g_w1lo;

    __shared__ __align__(16) char smem[SMEM_B];
    const uint32_t sb = (uint32_t)__cvta_generic_to_shared(smem);

    const int tid  = threadIdx.x;
    const int wid  = tid >> 5;
    const int lane = tid & 31;
    const int gid  = lane >> 2;        // groupID           (PTX fragment formulas)
    const int tig  = lane & 3;         // threadID_in_group
    const int m0 = blockIdx.y * BM;
    const int n0 = blockIdx.x * BN;

    // loader: each thread moves 2 A-chunks + 2 B-chunks of 16B per stage
    const int lrow = tid >> 2;          // 0..63 (i adds 64)
    const int lc   = tid & 3;           // 16B chunk within 64B of row data

    auto issue = [&](int c, int buf) {
        const int ph = c / CHPP;                 // 0,1,2
        const int kk = (c % CHPP) * BKC;
        const __nv_bfloat16* Ag = (ph == 1) ? Alo : Ahi;
        const __nv_bfloat16* Bg = (ph == 2) ? Blo : Bhi;
        const uint32_t base = sb + buf * STAGE_B;
#pragma unroll
        for (int i = 0; i < 2; ++i) {
            const int r = lrow + i * 64;
            const uint32_t off = (uint32_t)(r * ROWB + lc * 16);
            cp16(base + off,          Ag + (size_t)(m0 + r) * H_ + kk + lc * 8);
            cp16(base + TILE_B + off, Bg + (size_t)(n0 + r) * H_ + kk + lc * 8);
        }
        asm volatile("cp.async.commit_group;" ::: "memory");
    };

    // warp tile: 32 (m) x 64 (n)
    const int wm = (wid & 3) * 32;
    const int wn = (wid >> 2) * 64;

    float acc[2][8][4];
#pragma unroll
    for (int i = 0; i < 2; ++i)
#pragma unroll
        for (int j = 0; j < 8; ++j)
#pragma unroll
            for (int k = 0; k < 4; ++k) acc[i][j][k] = 0.f;

    issue(0, 0);
    issue(1, 1);

    for (int c = 0; c < NCH; ++c) {
        const int buf = c & 1;
        if (c + 1 < NCH) asm volatile("cp.async.wait_group 1;" ::: "memory");
        else             asm volatile("cp.async.wait_group 0;" ::: "memory");
        __syncthreads();

        const char* As = smem + buf * STAGE_B;
        const char* Bs = As + TILE_B;

#pragma unroll
        for (int kk2 = 0; kk2 < 2; ++kk2) {
            const int kc = (kk2 * 16 + tig * 2) * 2;     // byte col of k=tig*2
            // A fragments (PTX m16n8k16 A):
            //   a0:(gid, k) a1:(gid+8, k) a2:(gid, k+8) a3:(gid+8, k+8)
            uint32_t a[2][4];
#pragma unroll
            for (int mt = 0; mt < 2; ++mt) {
                const int r0 = wm + mt * 16 + gid;
                a[mt][0] = *(const uint32_t*)(As + r0 * ROWB + kc);
                a[mt][1] = *(const uint32_t*)(As + (r0 + 8) * ROWB + kc);
                a[mt][2] = *(const uint32_t*)(As + r0 * ROWB + kc + 16);
                a[mt][3] = *(const uint32_t*)(As + (r0 + 8) * ROWB + kc + 16);
            }
            // B fragments: b0:(k=tig*2, n=gid), b1:(k=tig*2+8, n=gid);
            // smem B is [n][k] (col-major KxN) as mma.row.col requires.
#pragma unroll
            for (int nt = 0; nt < 8; ++nt) {
                const int nr = wn + nt * 8 + gid;
                const uint32_t b0 = *(const uint32_t*)(Bs + nr * ROWB + kc);
                const uint32_t b1 = *(const uint32_t*)(Bs + nr * ROWB + kc + 16);
                mma_bf16(acc[0][nt], a[0], b0, b1);
                mma_bf16(acc[1][nt], a[1], b0, b1);
            }
        }
        __syncthreads();
        if (c + 2 < NCH) issue(c + 2, buf);
    }

    // Epilogue: PTX C layout: c0/c1 at (gid, tig*2 /+1), c2/c3 at (gid+8, ...)
#pragma unroll
    for (int mt = 0; mt < 2; ++mt) {
        const int r0 = m0 + wm + mt * 16 + gid;
#pragma unroll
        for (int nt = 0; nt < 8; ++nt) {
            const int col = n0 + wn + nt * 8 + tig * 2;
            const float bz0 = __ldg(&bias[col]);
            const float bz1 = __ldg(&bias[col + 1]);
            const float* a4 = acc[mt][nt];
            const float v00 = gelu_exact(a4[0] + bz0);
            const float v01 = gelu_exact(a4[1] + bz1);
            const float v10 = gelu_exact(a4[2] + bz0);
            const float v11 = gelu_exact(a4[3] + bz1);
            if (MODE == 0) {
                __nv_bfloat162 h0, l0, h1, l1;
                split_bf16(v00, h0.x, l0.x); split_bf16(v01, h0.y, l0.y);
                split_bf16(v10, h1.x, l1.x); split_bf16(v11, h1.y, l1.y);
                *(__nv_bfloat162*)(g_xhi + (size_t)r0 * H_ + col)       = h0;
                *(__nv_bfloat162*)(g_xlo + (size_t)r0 * H_ + col)       = l0;
                *(__nv_bfloat162*)(g_xhi + (size_t)(r0 + 8) * H_ + col) = h1;
                *(__nv_bfloat162*)(g_xlo + (size_t)(r0 + 8) * H_ + col) = l1;
            } else {
                *(float2*)(g_x2 + (size_t)r0 * H_ + col)       = make_float2(v00, v01);
                *(float2*)(g_x2 + (size_t)(r0 + 8) * H_ + col) = make_float2(v10, v11);
            }
        }
    }
}

// ---------------------------------------------------------------------------
// Kernel 4: out[row] = sigmoid(x2[row,:] . w3 + b3).  One warp per row.
// ---------------------------------------------------------------------------
__global__ __launch_bounds__(256) void head_kernel(const float* __restrict__ w3,
                                                   const float* __restrict__ b3,
                                                   float* __restrict__ out)
{
    const int row  = blockIdx.x * 8 + (threadIdx.x >> 5);
    const int lane = threadIdx.x & 31;
    const float4* x = (const float4*)(g_x2 + (size_t)row * H_);
    const float4* w = (const float4*)w3;

    float s = 0.f;
#pragma unroll
    for (int j = 0; j < 6; ++j) {
        const float4 a = x[lane + j * 32];
        const float4 b = w[lane + j * 32];
        s += a.x * b.x + a.y * b.y + a.z * b.z + a.w * b.w;
    }
#pragma unroll
    for (int o = 16; o > 0; o >>= 1) s += __shfl_xor_sync(0xffffffffu, s, o);

    if (lane == 0) {
        const float z = s + b3[0];
        out[row] = 1.0f / (1.0f + expf(-z));
    }
}

// ---------------------------------------------------------------------------
// Launch: wsplit(w1,w2) -> pool -> gemm<0> -> gemm<1> -> head.
// Only harness-provided d_in/d_out pointers cross the host->kernel boundary;
// all scratch is device-side symbols. Graph-capturable, allocation-free.
// ---------------------------------------------------------------------------
extern "C" void kernel_launch(void* const* d_in, const int* in_sizes, int n_in,
                              void* d_out, int out_size)
{
    const float* hidden = (const float*)d_in[0];
    const int*   sids   = (const int*)  d_in[1];
    const float* w1     = (const float*)d_in[2];
    const float* b1     = (const float*)d_in[3];
    const float* w2     = (const float*)d_in[4];
    const float* b2     = (const float*)d_in[5];
    const float* w3     = (const float*)d_in[6];
    const float* b3     = (const float*)d_in[7];
    float*       out    = (float*)d_out;

    dim3 wgrid(H_ / 32, H_ / 32);     // (24, 24)
    dim3 wblk(32, 8);
    wsplit_kernel<<<wgrid, wblk>>>(w1, 0);
    wsplit_kernel<<<wgrid, wblk>>>(w2, 1);

    pool_kernel<<<M_, 256>>>(hidden, sids);            // -> g_ahi / g_alo

    dim3 grid(H_ / BN, M_ / BM);                        // (6, 64)
    gemm_mma_kernel<0><<<grid, 256>>>(b1);              // -> g_xhi / g_xlo
    gemm_mma_kernel<1><<<grid, 256>>>(b2);              // -> g_x2

    head_kernel<<<M_ / 8, 256>>>(w3, b3, out);          // g_x2 -> out
}

// round 12
// speedup vs baseline: 1.5978x; 1.1732x over previous
#include <cuda_runtime.h>
#include <cuda_bf16.h>
#include <cstdint>

// Problem constants
#define B_  64
#define T_  512
#define H_  768
#define S_  128
#define M_  (B_ * S_)          // 8192 rows through the MLP

// GEMM tiling (warp-level mma.sync)
#define BM 128
#define BN 128
#define BKC 64                     // bf16 K per chunk
#define KPHASES 3                  // Ahi*Bhi + Alo*Bhi + Ahi*Blo
#define CHPP (H_ / BKC)            // 12 chunks per phase
#define NCH (KPHASES * CHPP)       // 36 chunks over K_eff = 2304

// Padded, UN-swizzled smem tiles: 128 rows x (64 bf16 data + 8 pad) = 144 bytes.
// Row stride 144B = 36 words ≡ 4 (mod 32): 8-row ldmatrix phases are
// bank-conflict-free (banks 0,4,8,...,28 each covering 4 consecutive words).
#define ROWB    144
#define TILE_B  (128 * ROWB)        // 18432
#define STAGE_B (2 * TILE_B)        // 36864 (A tile + B tile)
#define SMEM_B  (2 * STAGE_B)       // 73728, double buffered (dynamic, opt-in)

// Scratch (no allocation allowed -> __device__ globals).
// CRITICAL: referenced ONLY inside device code. Passing a __device__ global as
// a kernel argument from host code passes the HOST shadow symbol's address;
// on GB300 (HMM/ATS) that address is GPU-dereferenceable, so kernels silently
// read zero-filled host .bss -- the R6-R10 failure mode.
__device__ __align__(128) __nv_bfloat16 g_ahi[M_ * H_];
__device__ __align__(128) __nv_bfloat16 g_alo[M_ * H_];
__device__ __align__(128) __nv_bfloat16 g_xhi[M_ * H_];
__device__ __align__(128) __nv_bfloat16 g_xlo[M_ * H_];
__device__ __align__(128) __nv_bfloat16 g_w1hi[H_ * H_];
__device__ __align__(128) __nv_bfloat16 g_w1lo[H_ * H_];
__device__ __align__(128) __nv_bfloat16 g_w2hi[H_ * H_];
__device__ __align__(128) __nv_bfloat16 g_w2lo[H_ * H_];
__device__ __align__(128) float g_x2[M_ * H_];

// ---------------------------------------------------------------------------
// Helpers
// ---------------------------------------------------------------------------
__device__ __forceinline__ void cp16(uint32_t smem, const void* gmem)
{
    asm volatile("cp.async.cg.shared.global [%0], [%1], 16;\n"
                 :: "r"(smem), "l"(gmem) : "memory");
}

__device__ __forceinline__ void ldsm_x4(uint32_t* r, uint32_t addr)
{
    asm volatile("ldmatrix.sync.aligned.m8n8.x4.shared.b16 {%0,%1,%2,%3}, [%4];"
                 : "=r"(r[0]), "=r"(r[1]), "=r"(r[2]), "=r"(r[3]) : "r"(addr));
}

__device__ __forceinline__ void mma_bf16(float* d, const uint32_t* a,
                                         uint32_t b0, uint32_t b1)
{
    asm volatile(
        "mma.sync.aligned.m16n8k16.row.col.f32.bf16.bf16.f32 "
        "{%0,%1,%2,%3}, {%4,%5,%6,%7}, {%8,%9}, {%0,%1,%2,%3};"
        : "+f"(d[0]), "+f"(d[1]), "+f"(d[2]), "+f"(d[3])
        : "r"(a[0]), "r"(a[1]), "r"(a[2]), "r"(a[3]), "r"(b0), "r"(b1));
}

__device__ __forceinline__ float gelu_exact(float x)
{
    return 0.5f * x * (1.0f + erff(x * 0.70710678118654752f));
}

__device__ __forceinline__ void split_bf16(float v, __nv_bfloat16& h, __nv_bfloat16& l)
{
    h = __float2bfloat16(v);
    l = __float2bfloat16(v - __bfloat162float(h));
}

// ---------------------------------------------------------------------------
// Kernel 1: per-(batch, statement) mean pooling -> split bf16 (g_ahi/g_alo).
// Sorted ids -> contiguous token range via binary search. One block per (b,s).
// ---------------------------------------------------------------------------
__global__ __launch_bounds__(256) void pool_kernel(const float* __restrict__ hidden,
                                                   const int*   __restrict__ sids)
{
    const int bs = blockIdx.x;
    const int b  = bs >> 7;
    const int s  = bs & (S_ - 1);

    __shared__ int s_lo, s_hi;
    if (threadIdx.x == 0) {
        const int* ids = sids + b * T_;
        int lo = 0, hi = T_;
        while (lo < hi) { int m = (lo + hi) >> 1; if (ids[m] < s) lo = m + 1; else hi = m; }
        s_lo = lo;
        hi = T_;
        while (lo < hi) { int m = (lo + hi) >> 1; if (ids[m] < s + 1) lo = m + 1; else hi = m; }
        s_hi = lo;
    }
    __syncthreads();

    const int lo  = s_lo;
    const int cnt = s_hi - s_lo;
    const float inv = 1.0f / (float)max(cnt, 1);

    const int c = threadIdx.x;
    float a0 = 0.f, a1 = 0.f, a2 = 0.f;
    const float* row = hidden + ((size_t)b * T_ + lo) * H_;
    for (int t = 0; t < cnt; ++t, row += H_) {
        a0 += row[c];
        a1 += row[c + 256];
        a2 += row[c + 512];
    }
    const size_t o = (size_t)bs * H_;
    __nv_bfloat16 h, l;
    split_bf16(a0 * inv, h, l); g_ahi[o + c]       = h; g_alo[o + c]       = l;
    split_bf16(a1 * inv, h, l); g_ahi[o + c + 256] = h; g_alo[o + c + 256] = l;
    split_bf16(a2 * inv, h, l); g_ahi[o + c + 512] = h; g_alo[o + c + 512] = l;
}

// ---------------------------------------------------------------------------
// Kernel 2: weight transpose + bf16 split.  W[k][n] -> hi/lo[n][k].
// which==0 -> g_w1hi/g_w1lo, which==1 -> g_w2hi/g_w2lo (selected in device code).
// ---------------------------------------------------------------------------
__global__ __launch_bounds__(256) void wsplit_kernel(const float* __restrict__ W,
                                                     int which)
{
    __nv_bfloat16* hi = which ? g_w2hi : g_w1hi;
    __nv_bfloat16* lo = which ? g_w2lo : g_w1lo;

    __shared__ float tile[32][33];
    const int kb = blockIdx.y * 32, nb = blockIdx.x * 32;
    const int tx = threadIdx.x, ty = threadIdx.y;   // 32 x 8

#pragma unroll
    for (int i = ty; i < 32; i += 8)
        tile[i][tx] = W[(size_t)(kb + i) * H_ + nb + tx];
    __syncthreads();
#pragma unroll
    for (int i = ty; i < 32; i += 8) {
        const float v = tile[tx][i];               // W[kb+tx][nb+i]
        const size_t o = (size_t)(nb + i) * H_ + kb + tx;
        __nv_bfloat16 h, l;
        split_bf16(v, h, l);
        hi[o] = h;
        lo[o] = l;
    }
}

// ---------------------------------------------------------------------------
// Kernel 3: bf16 mma.sync GEMM + bias + exact GELU.
// K_eff = 3*H via phases: [Ahi|Alo|Ahi] . [Bhi|Bhi|Blo] (fp32-accurate product;
// only the Alo*Blo term ~2^-16 relative is dropped).
// CTA 128x128, 8 warps of 32x64, BKC=64, cp.async double buffer.
// Fragments via ldmatrix.x4 (addresses transcribe the PTX m16n8k16 formulas;
// 144B rows keep every 8-row phase bank-conflict-free).
// MODE 0: A=g_ahi/g_alo, B=g_w1*, out split bf16 -> g_xhi/g_xlo.
// MODE 1: A=g_xhi/g_xlo, B=g_w2*, out fp32 -> g_x2.
// ---------------------------------------------------------------------------
template <int MODE>
__global__ __launch_bounds__(256, 2) void gemm_mma_kernel(const float* __restrict__ bias)
{
    const __nv_bfloat16* __restrict__ Ahi = MODE ? g_xhi : g_ahi;
    const __nv_bfloat16* __restrict__ Alo = MODE ? g_xlo : g_alo;
    const __nv_bfloat16* __restrict__ Bhi = MODE ? g_w2hi : g_w1hi;
    const __nv_bfloat16* __restrict__ Blo = MODE ? g_w2lo : g_w1lo;

    extern __shared__ __align__(16) char smem[];
    const uint32_t sb = (uint32_t)__cvta_generic_to_shared(smem);

    const int tid  = threadIdx.x;
    const int wid  = tid >> 5;
    const int lane = tid & 31;
    const int gid  = lane >> 2;        // groupID           (PTX fragment formulas)
    const int tig  = lane & 3;         // threadID_in_group
    const int m0 = blockIdx.y * BM;
    const int n0 = blockIdx.x * BN;

    // loader: 128 rows x 8 chunks(16B) per tile = 1024 chunks / 256 thr = 4 each
    auto issue = [&](int c, int buf) {
        const int ph = c / CHPP;                 // 0,1,2
        const int kk = (c % CHPP) * BKC;
        const __nv_bfloat16* Ag = (ph == 1) ? Alo : Ahi;
        const __nv_bfloat16* Bg = (ph == 2) ? Blo : Bhi;
        const uint32_t base = sb + buf * STAGE_B;
#pragma unroll
        for (int i = 0; i < 4; ++i) {
            const int idx = tid + i * 256;       // 0..1023
            const int r   = idx >> 3;            // row 0..127
            const int cc  = idx & 7;             // 16B chunk 0..7
            const uint32_t off = (uint32_t)(r * ROWB + cc * 16);
            cp16(base + off,          Ag + (size_t)(m0 + r) * H_ + kk + cc * 8);
            cp16(base + TILE_B + off, Bg + (size_t)(n0 + r) * H_ + kk + cc * 8);
        }
        asm volatile("cp.async.commit_group;" ::: "memory");
    };

    // warp tile: 32 (m) x 64 (n)
    const int wm = (wid & 3) * 32;
    const int wn = (wid >> 2) * 64;

    // ldmatrix.x4 lane addressing: lanes 0-7 -> rows 0-7 (byte 0), 8-15 ->
    // rows 8-15 (byte 0), 16-23 -> rows 0-7 (byte 16), 24-31 -> rows 8-15
    // (byte 16). Yields regs m0..m3 = (r0-7,k0-7),(r8-15,k0-7),(r0-7,k8-15),
    // (r8-15,k8-15) -- exactly the a0..a3 / paired-b fragment order.
    const int lm_row = lane & 15;
    const int lm_col = (lane >> 4) * 16;

    float acc[2][8][4];
#pragma unroll
    for (int i = 0; i < 2; ++i)
#pragma unroll
        for (int j = 0; j < 8; ++j)
#pragma unroll
            for (int k = 0; k < 4; ++k) acc[i][j][k] = 0.f;

    issue(0, 0);
    issue(1, 1);

    for (int c = 0; c < NCH; ++c) {
        const int buf = c & 1;
        if (c + 1 < NCH) asm volatile("cp.async.wait_group 1;" ::: "memory");
        else             asm volatile("cp.async.wait_group 0;" ::: "memory");
        __syncthreads();

        const uint32_t As = sb + buf * STAGE_B;
        const uint32_t Bs = As + TILE_B;

#pragma unroll
        for (int kk2 = 0; kk2 < 4; ++kk2) {
            const uint32_t kb = kk2 * 32 + lm_col;      // byte col within row
            uint32_t a[2][4];
            ldsm_x4(a[0], As + (uint32_t)((wm + lm_row) * ROWB) + kb);
            ldsm_x4(a[1], As + (uint32_t)((wm + 16 + lm_row) * ROWB) + kb);
#pragma unroll
            for (int g = 0; g < 4; ++g) {
                uint32_t bb[4];   // m0:(n0-7,k0-7) m1:(n8-15,k0-7) m2:(n0-7,k8-15) m3:(n8-15,k8-15)
                ldsm_x4(bb, Bs + (uint32_t)((wn + g * 16 + lm_row) * ROWB) + kb);
                mma_bf16(acc[0][2 * g],     a[0], bb[0], bb[2]);
                mma_bf16(acc[0][2 * g + 1], a[0], bb[1], bb[3]);
                mma_bf16(acc[1][2 * g],     a[1], bb[0], bb[2]);
                mma_bf16(acc[1][2 * g + 1], a[1], bb[1], bb[3]);
            }
        }
        __syncthreads();
        if (c + 2 < NCH) issue(c + 2, buf);
    }

    // Epilogue: PTX C layout: c0/c1 at (gid, tig*2 /+1), c2/c3 at (gid+8, ...)
#pragma unroll
    for (int mt = 0; mt < 2; ++mt) {
        const int r0 = m0 + wm + mt * 16 + gid;
#pragma unroll
        for (int nt = 0; nt < 8; ++nt) {
            const int col = n0 + wn + nt * 8 + tig * 2;
            const float bz0 = __ldg(&bias[col]);
            const float bz1 = __ldg(&bias[col + 1]);
            const float* a4 = acc[mt][nt];
            const float v00 = gelu_exact(a4[0] + bz0);
            const float v01 = gelu_exact(a4[1] + bz1);
            const float v10 = gelu_exact(a4[2] + bz0);
            const float v11 = gelu_exact(a4[3] + bz1);
            if (MODE == 0) {
                __nv_bfloat162 h0, l0, h1, l1;
                split_bf16(v00, h0.x, l0.x); split_bf16(v01, h0.y, l0.y);
                split_bf16(v10, h1.x, l1.x); split_bf16(v11, h1.y, l1.y);
                *(__nv_bfloat162*)(g_xhi + (size_t)r0 * H_ + col)       = h0;
                *(__nv_bfloat162*)(g_xlo + (size_t)r0 * H_ + col)       = l0;
                *(__nv_bfloat162*)(g_xhi + (size_t)(r0 + 8) * H_ + col) = h1;
                *(__nv_bfloat162*)(g_xlo + (size_t)(r0 + 8) * H_ + col) = l1;
            } else {
                *(float2*)(g_x2 + (size_t)r0 * H_ + col)       = make_float2(v00, v01);
                *(float2*)(g_x2 + (size_t)(r0 + 8) * H_ + col) = make_float2(v10, v11);
            }
        }
    }
}

// ---------------------------------------------------------------------------
// Kernel 4: out[row] = sigmoid(x2[row,:] . w3 + b3).  One warp per row.
// ---------------------------------------------------------------------------
__global__ __launch_bounds__(256) void head_kernel(const float* __restrict__ w3,
                                                   const float* __restrict__ b3,
                                                   float* __restrict__ out)
{
    const int row  = blockIdx.x * 8 + (threadIdx.x >> 5);
    const int lane = threadIdx.x & 31;
    const float4* x = (const float4*)(g_x2 + (size_t)row * H_);
    const float4* w = (const float4*)w3;

    float s = 0.f;
#pragma unroll
    for (int j = 0; j < 6; ++j) {
        const float4 a = x[lane + j * 32];
        const float4 b = w[lane + j * 32];
        s += a.x * b.x + a.y * b.y + a.z * b.z + a.w * b.w;
    }
#pragma unroll
    for (int o = 16; o > 0; o >>= 1) s += __shfl_xor_sync(0xffffffffu, s, o);

    if (lane == 0) {
        const float z = s + b3[0];
        out[row] = 1.0f / (1.0f + expf(-z));
    }
}

// ---------------------------------------------------------------------------
// Launch: wsplit(w1,w2) -> pool -> gemm<0> -> gemm<1> -> head.
// Only harness-provided d_in/d_out pointers cross the host->kernel boundary;
// all scratch is device-side symbols. Graph-capturable, allocation-free.
// ---------------------------------------------------------------------------
extern "C" void kernel_launch(void* const* d_in, const int* in_sizes, int n_in,
                              void* d_out, int out_size)
{
    const float* hidden = (const float*)d_in[0];
    const int*   sids   = (const int*)  d_in[1];
    const float* w1     = (const float*)d_in[2];
    const float* b1     = (const float*)d_in[3];
    const float* w2     = (const float*)d_in[4];
    const float* b2     = (const float*)d_in[5];
    const float* w3     = (const float*)d_in[6];
    const float* b3     = (const float*)d_in[7];
    float*       out    = (float*)d_out;

    cudaFuncSetAttribute(gemm_mma_kernel<0>,
                         cudaFuncAttributeMaxDynamicSharedMemorySize, SMEM_B);
    cudaFuncSetAttribute(gemm_mma_kernel<1>,
                         cudaFuncAttributeMaxDynamicSharedMemorySize, SMEM_B);

    dim3 wgrid(H_ / 32, H_ / 32);     // (24, 24)
    dim3 wblk(32, 8);
    wsplit_kernel<<<wgrid, wblk>>>(w1, 0);
    wsplit_kernel<<<wgrid, wblk>>>(w2, 1);

    pool_kernel<<<M_, 256>>>(hidden, sids);            // -> g_ahi / g_alo

    dim3 grid(H_ / BN, M_ / BM);                        // (6, 64)
    gemm_mma_kernel<0><<<grid, 256, SMEM_B>>>(b1);      // -> g_xhi / g_xlo
    gemm_mma_kernel<1><<<grid, 256, SMEM_B>>>(b2);      // -> g_x2

    head_kernel<<<M_ / 8, 256>>>(w3, b3, out);          // g_x2 -> out
}

// round 13
// speedup vs baseline: 1.6695x; 1.0448x over previous
#include <cuda_runtime.h>
#include <cuda_bf16.h>
#include <cstdint>

// Problem constants
#define B_  64
#define T_  512
#define H_  768
#define S_  128
#define M_  (B_ * S_)          // 8192 rows through the MLP

// GEMM tiling (warp-level mma.sync, fused 3-product split-bf16)
#define BM 128
#define BN 192                     // grid = (768/192) x (8192/128) = 256 CTAs -> 1 wave
#define BKC 32                     // bf16 K per chunk
#define NCH (H_ / BKC)             // 24 chunks

// Padded, UN-swizzled smem rows: 32 bf16 data (64B) + 16B pad = 80B.
// Stride 20 words == 20 (mod 32): all 8-row ldmatrix phases and cp.async
// write patterns are bank-conflict-free (verified bank walk).
#define ROWB     80
#define A_TILE   (128 * ROWB)            // 10240 (one of hi/lo)
#define B_TILE   (192 * ROWB)            // 15360
#define OFF_AHI  0
#define OFF_ALO  (A_TILE)
#define OFF_BHI  (2 * A_TILE)
#define OFF_BLO  (2 * A_TILE + B_TILE)
#define STAGE_B  (2 * A_TILE + 2 * B_TILE)   // 51200
#define SMEM_B   (2 * STAGE_B)               // 102400, double buffered

// Scratch (no allocation allowed -> __device__ globals).
// CRITICAL: referenced ONLY inside device code. Passing a __device__ global as
// a kernel argument from host code passes the HOST shadow symbol's address;
// on GB300 (HMM/ATS) that address is GPU-dereferenceable, so kernels silently
// read zero-filled host .bss -- the R6-R10 failure mode.
__device__ __align__(128) __nv_bfloat16 g_ahi[M_ * H_];
__device__ __align__(128) __nv_bfloat16 g_alo[M_ * H_];
__device__ __align__(128) __nv_bfloat16 g_xhi[M_ * H_];
__device__ __align__(128) __nv_bfloat16 g_xlo[M_ * H_];
__device__ __align__(128) __nv_bfloat16 g_w1hi[H_ * H_];
__device__ __align__(128) __nv_bfloat16 g_w1lo[H_ * H_];
__device__ __align__(128) __nv_bfloat16 g_w2hi[H_ * H_];
__device__ __align__(128) __nv_bfloat16 g_w2lo[H_ * H_];
__device__ __align__(128) float g_x2[M_ * H_];

// ---------------------------------------------------------------------------
// Helpers
// ---------------------------------------------------------------------------
__device__ __forceinline__ void cp16(uint32_t smem, const void* gmem)
{
    asm volatile("cp.async.cg.shared.global [%0], [%1], 16;\n"
                 :: "r"(smem), "l"(gmem) : "memory");
}

__device__ __forceinline__ void ldsm_x4(uint32_t* r, uint32_t addr)
{
    asm volatile("ldmatrix.sync.aligned.m8n8.x4.shared.b16 {%0,%1,%2,%3}, [%4];"
                 : "=r"(r[0]), "=r"(r[1]), "=r"(r[2]), "=r"(r[3]) : "r"(addr));
}

__device__ __forceinline__ void mma_bf16(float* d, const uint32_t* a,
                                         uint32_t b0, uint32_t b1)
{
    asm volatile(
        "mma.sync.aligned.m16n8k16.row.col.f32.bf16.bf16.f32 "
        "{%0,%1,%2,%3}, {%4,%5,%6,%7}, {%8,%9}, {%0,%1,%2,%3};"
        : "+f"(d[0]), "+f"(d[1]), "+f"(d[2]), "+f"(d[3])
        : "r"(a[0]), "r"(a[1]), "r"(a[2]), "r"(a[3]), "r"(b0), "r"(b1));
}

__device__ __forceinline__ float gelu_exact(float x)
{
    return 0.5f * x * (1.0f + erff(x * 0.70710678118654752f));
}

__device__ __forceinline__ void split_bf16(float v, __nv_bfloat16& h, __nv_bfloat16& l)
{
    h = __float2bfloat16(v);
    l = __float2bfloat16(v - __bfloat162float(h));
}

// ---------------------------------------------------------------------------
// Kernel 1: per-(batch, statement) mean pooling -> split bf16 (g_ahi/g_alo).
// Sorted ids -> contiguous token range via binary search. One block per (b,s).
// ---------------------------------------------------------------------------
__global__ __launch_bounds__(256) void pool_kernel(const float* __restrict__ hidden,
                                                   const int*   __restrict__ sids)
{
    const int bs = blockIdx.x;
    const int b  = bs >> 7;
    const int s  = bs & (S_ - 1);

    __shared__ int s_lo, s_hi;
    if (threadIdx.x == 0) {
        const int* ids = sids + b * T_;
        int lo = 0, hi = T_;
        while (lo < hi) { int m = (lo + hi) >> 1; if (ids[m] < s) lo = m + 1; else hi = m; }
        s_lo = lo;
        hi = T_;
        while (lo < hi) { int m = (lo + hi) >> 1; if (ids[m] < s + 1) lo = m + 1; else hi = m; }
        s_hi = lo;
    }
    __syncthreads();

    const int lo  = s_lo;
    const int cnt = s_hi - s_lo;
    const float inv = 1.0f / (float)max(cnt, 1);

    const int c = threadIdx.x;
    float a0 = 0.f, a1 = 0.f, a2 = 0.f;
    const float* row = hidden + ((size_t)b * T_ + lo) * H_;
    for (int t = 0; t < cnt; ++t, row += H_) {
        a0 += row[c];
        a1 += row[c + 256];
        a2 += row[c + 512];
    }
    const size_t o = (size_t)bs * H_;
    __nv_bfloat16 h, l;
    split_bf16(a0 * inv, h, l); g_ahi[o + c]       = h; g_alo[o + c]       = l;
    split_bf16(a1 * inv, h, l); g_ahi[o + c + 256] = h; g_alo[o + c + 256] = l;
    split_bf16(a2 * inv, h, l); g_ahi[o + c + 512] = h; g_alo[o + c + 512] = l;
}

// ---------------------------------------------------------------------------
// Kernel 2: weight transpose + bf16 split.  W[k][n] -> hi/lo[n][k].
// which==0 -> g_w1hi/g_w1lo, which==1 -> g_w2hi/g_w2lo (selected in device code).
// ---------------------------------------------------------------------------
__global__ __launch_bounds__(256) void wsplit_kernel(const float* __restrict__ W,
                                                     int which)
{
    __nv_bfloat16* hi = which ? g_w2hi : g_w1hi;
    __nv_bfloat16* lo = which ? g_w2lo : g_w1lo;

    __shared__ float tile[32][33];
    const int kb = blockIdx.y * 32, nb = blockIdx.x * 32;
    const int tx = threadIdx.x, ty = threadIdx.y;   // 32 x 8

#pragma unroll
    for (int i = ty; i < 32; i += 8)
        tile[i][tx] = W[(size_t)(kb + i) * H_ + nb + tx];
    __syncthreads();
#pragma unroll
    for (int i = ty; i < 32; i += 8) {
        const float v = tile[tx][i];               // W[kb+tx][nb+i]
        const size_t o = (size_t)(nb + i) * H_ + kb + tx;
        __nv_bfloat16 h, l;
        split_bf16(v, h, l);
        hi[o] = h;
        lo[o] = l;
    }
}

// ---------------------------------------------------------------------------
// Kernel 3: fused split-bf16 mma.sync GEMM + bias + exact GELU.
// Per K-chunk, all three products on once-loaded tiles:
//   acc += Ahi.Bhi + Alo.Bhi + Ahi.Blo      (drops only Alo.Blo ~2^-16 rel)
// CTA 128x192, 8 warps of 32x96, BKC=32, cp.async double buffer, single wave.
// MODE 0: A=g_ahi/g_alo, B=g_w1*, out split bf16 -> g_xhi/g_xlo.
// MODE 1: A=g_xhi/g_xlo, B=g_w2*, out fp32 -> g_x2.
// ---------------------------------------------------------------------------
template <int MODE>
__global__ __launch_bounds__(256, 2) void gemm_mma_kernel(const float* __restrict__ bias)
{
    const __nv_bfloat16* __restrict__ Ahi = MODE ? g_xhi : g_ahi;
    const __nv_bfloat16* __restrict__ Alo = MODE ? g_xlo : g_alo;
    const __nv_bfloat16* __restrict__ Bhi = MODE ? g_w2hi : g_w1hi;
    const __nv_bfloat16* __restrict__ Blo = MODE ? g_w2lo : g_w1lo;

    extern __shared__ __align__(16) char smem[];
    const uint32_t sb = (uint32_t)__cvta_generic_to_shared(smem);

    const int tid  = threadIdx.x;
    const int wid  = tid >> 5;
    const int lane = tid & 31;
    const int gid  = lane >> 2;        // groupID           (PTX fragment formulas)
    const int tig  = lane & 3;         // threadID_in_group
    const int m0 = blockIdx.y * BM;
    const int n0 = blockIdx.x * BN;

    // loader: A 1024 chunks of 16B (hi+lo), B 1536 chunks (hi+lo); 10/thread.
    auto issue = [&](int c, int buf) {
        const int kk = c * BKC;
        const uint32_t base = sb + buf * STAGE_B;
#pragma unroll
        for (int i = 0; i < 4; ++i) {                // A: 2 tiles x 128 rows x 4
            const int idx  = tid + i * 256;          // 0..1023
            const int tile = idx >> 9;               // 0=hi, 1=lo
            const int r    = (idx >> 2) & 127;
            const int cc   = idx & 3;
            const __nv_bfloat16* src = (tile ? Alo : Ahi)
                                     + (size_t)(m0 + r) * H_ + kk + cc * 8;
            cp16(base + tile * A_TILE + (uint32_t)(r * ROWB + cc * 16), src);
        }
#pragma unroll
        for (int i = 0; i < 6; ++i) {                // B: 2 tiles x 192 rows x 4
            const int idx  = tid + i * 256;          // 0..1535
            const int tile = idx / 768;              // 0=hi, 1=lo
            const int rr   = idx - tile * 768;
            const int r    = rr >> 2;
            const int cc   = rr & 3;
            const __nv_bfloat16* src = (tile ? Blo : Bhi)
                                     + (size_t)(n0 + r) * H_ + kk + cc * 8;
            cp16(base + OFF_BHI + tile * B_TILE + (uint32_t)(r * ROWB + cc * 16), src);
        }
        asm volatile("cp.async.commit_group;" ::: "memory");
    };

    // warp tile: 32 (m) x 96 (n);  8 warps = 4m x 2n
    const int wm = (wid & 3) * 32;
    const int wn = (wid >> 2) * 96;

    // ldmatrix.x4 lane addressing (same audited mapping as R12):
    // lanes 0-15 -> rows 0-15 at byte 0; lanes 16-31 -> rows 0-15 at byte 16.
    const int lm_row = lane & 15;
    const int lm_col = (lane >> 4) * 16;

    float acc[2][12][4];
#pragma unroll
    for (int i = 0; i < 2; ++i)
#pragma unroll
        for (int j = 0; j < 12; ++j)
#pragma unroll
            for (int k = 0; k < 4; ++k) acc[i][j][k] = 0.f;

    issue(0, 0);
    issue(1, 1);

    for (int c = 0; c < NCH; ++c) {
        const int buf = c & 1;
        if (c + 1 < NCH) asm volatile("cp.async.wait_group 1;" ::: "memory");
        else             asm volatile("cp.async.wait_group 0;" ::: "memory");
        __syncthreads();

        const uint32_t st = sb + buf * STAGE_B;
        const uint32_t a_row = (uint32_t)((wm + lm_row) * ROWB) + lm_col;
        const uint32_t b_row = (uint32_t)((wn + lm_row) * ROWB) + lm_col;

#pragma unroll
        for (int kk2 = 0; kk2 < 2; ++kk2) {
            const uint32_t kb = kk2 * 32;           // byte offset of k16 half
            uint32_t ahi[2][4], alo[2][4];
            ldsm_x4(ahi[0], st + OFF_AHI + a_row + kb);
            ldsm_x4(ahi[1], st + OFF_AHI + a_row + 16 * ROWB + kb);
            ldsm_x4(alo[0], st + OFF_ALO + a_row + kb);
            ldsm_x4(alo[1], st + OFF_ALO + a_row + 16 * ROWB + kb);
#pragma unroll
            for (int g = 0; g < 6; ++g) {           // n-groups of 16
                uint32_t bh[4], bl[4];
                // regs: m0:(n0-7,k0-7) m1:(n8-15,k0-7) m2:(n0-7,k8-15) m3:(n8-15,k8-15)
                ldsm_x4(bh, st + OFF_BHI + b_row + (uint32_t)(g * 16 * ROWB) + kb);
                ldsm_x4(bl, st + OFF_BLO + b_row + (uint32_t)(g * 16 * ROWB) + kb);
#pragma unroll
                for (int mt = 0; mt < 2; ++mt) {
                    mma_bf16(acc[mt][2 * g],     ahi[mt], bh[0], bh[2]);
                    mma_bf16(acc[mt][2 * g + 1], ahi[mt], bh[1], bh[3]);
                    mma_bf16(acc[mt][2 * g],     alo[mt], bh[0], bh[2]);
                    mma_bf16(acc[mt][2 * g + 1], alo[mt], bh[1], bh[3]);
                    mma_bf16(acc[mt][2 * g],     ahi[mt], bl[0], bl[2]);
                    mma_bf16(acc[mt][2 * g + 1], ahi[mt], bl[1], bl[3]);
                }
            }
        }
        __syncthreads();
        if (c + 2 < NCH) issue(c + 2, buf);
    }

    // Epilogue: PTX C layout: c0/c1 at (gid, tig*2 /+1), c2/c3 at (gid+8, ...)
#pragma unroll
    for (int mt = 0; mt < 2; ++mt) {
        const int r0 = m0 + wm + mt * 16 + gid;
#pragma unroll
        for (int nt = 0; nt < 12; ++nt) {
            const int col = n0 + wn + nt * 8 + tig * 2;
            const float bz0 = __ldg(&bias[col]);
            const float bz1 = __ldg(&bias[col + 1]);
            const float* a4 = acc[mt][nt];
            const float v00 = gelu_exact(a4[0] + bz0);
            const float v01 = gelu_exact(a4[1] + bz1);
            const float v10 = gelu_exact(a4[2] + bz0);
            const float v11 = gelu_exact(a4[3] + bz1);
            if (MODE == 0) {
                __nv_bfloat162 h0, l0, h1, l1;
                split_bf16(v00, h0.x, l0.x); split_bf16(v01, h0.y, l0.y);
                split_bf16(v10, h1.x, l1.x); split_bf16(v11, h1.y, l1.y);
                *(__nv_bfloat162*)(g_xhi + (size_t)r0 * H_ + col)       = h0;
                *(__nv_bfloat162*)(g_xlo + (size_t)r0 * H_ + col)       = l0;
                *(__nv_bfloat162*)(g_xhi + (size_t)(r0 + 8) * H_ + col) = h1;
                *(__nv_bfloat162*)(g_xlo + (size_t)(r0 + 8) * H_ + col) = l1;
            } else {
                *(float2*)(g_x2 + (size_t)r0 * H_ + col)       = make_float2(v00, v01);
                *(float2*)(g_x2 + (size_t)(r0 + 8) * H_ + col) = make_float2(v10, v11);
            }
        }
    }
}

// ---------------------------------------------------------------------------
// Kernel 4: out[row] = sigmoid(x2[row,:] . w3 + b3).  One warp per row.
// ---------------------------------------------------------------------------
__global__ __launch_bounds__(256) void head_kernel(const float* __restrict__ w3,
                                                   const float* __restrict__ b3,
                                                   float* __restrict__ out)
{
    const int row  = blockIdx.x * 8 + (threadIdx.x >> 5);
    const int lane = threadIdx.x & 31;
    const float4* x = (const float4*)(g_x2 + (size_t)row * H_);
    const float4* w = (const float4*)w3;

    float s = 0.f;
#pragma unroll
    for (int j = 0; j < 6; ++j) {
        const float4 a = x[lane + j * 32];
        const float4 b = w[lane + j * 32];
        s += a.x * b.x + a.y * b.y + a.z * b.z + a.w * b.w;
    }
#pragma unroll
    for (int o = 16; o > 0; o >>= 1) s += __shfl_xor_sync(0xffffffffu, s, o);

    if (lane == 0) {
        const float z = s + b3[0];
        out[row] = 1.0f / (1.0f + expf(-z));
    }
}

// ---------------------------------------------------------------------------
// Launch: wsplit(w1,w2) -> pool -> gemm<0> -> gemm<1> -> head.
// Only harness-provided d_in/d_out pointers cross the host->kernel boundary;
// all scratch is device-side symbols. Graph-capturable, allocation-free.
// ---------------------------------------------------------------------------
extern "C" void kernel_launch(void* const* d_in, const int* in_sizes, int n_in,
                              void* d_out, int out_size)
{
    const float* hidden = (const float*)d_in[0];
    const int*   sids   = (const int*)  d_in[1];
    const float* w1     = (const float*)d_in[2];
    const float* b1     = (const float*)d_in[3];
    const float* w2     = (const float*)d_in[4];
    const float* b2     = (const float*)d_in[5];
    const float* w3     = (const float*)d_in[6];
    const float* b3     = (const float*)d_in[7];
    float*       out    = (float*)d_out;

    cudaFuncSetAttribute(gemm_mma_kernel<0>,
                         cudaFuncAttributeMaxDynamicSharedMemorySize, SMEM_B);
    cudaFuncSetAttribute(gemm_mma_kernel<1>,
                         cudaFuncAttributeMaxDynamicSharedMemorySize, SMEM_B);

    dim3 wgrid(H_ / 32, H_ / 32);     // (24, 24)
    dim3 wblk(32, 8);
    wsplit_kernel<<<wgrid, wblk>>>(w1, 0);
    wsplit_kernel<<<wgrid, wblk>>>(w2, 1);

    pool_kernel<<<M_, 256>>>(hidden, sids);            // -> g_ahi / g_alo

    dim3 grid(H_ / BN, M_ / BM);                        // (4, 64) = 256 CTAs
    gemm_mma_kernel<0><<<grid, 256, SMEM_B>>>(b1);      // -> g_xhi / g_xlo
    gemm_mma_kernel<1><<<grid, 256, SMEM_B>>>(b2);      // -> g_x2

    head_kernel<<<M_ / 8, 256>>>(w3, b3, out);          // g_x2 -> out
}

// round 14
// speedup vs baseline: 1.7023x; 1.0196x over previous
#include <cuda_runtime.h>
#include <cuda_bf16.h>
#include <cstdint>

// Problem constants
#define B_  64
#define T_  512
#define H_  768
#define S_  128
#define M_  (B_ * S_)          // 8192 rows through the MLP

// GEMM tiling (warp-level mma.sync, fused 3-product split-bf16)
#define BM 128
#define BN 192                     // grid = (768/192) x (8192/128) = 256 CTAs -> 1 wave
#define BKC 32                     // bf16 K per chunk
#define NCH (H_ / BKC)             // 24 chunks

// Padded, UN-swizzled smem rows: 32 bf16 data (64B) + 16B pad = 80B.
// Stride 20 words == 20 (mod 32): all 8-row ldmatrix phases and cp.async
// write patterns are bank-conflict-free (verified bank walk).
#define ROWB     80
#define A_TILE   (128 * ROWB)            // 10240 (one of hi/lo)
#define B_TILE   (192 * ROWB)            // 15360
#define OFF_AHI  0
#define OFF_ALO  (A_TILE)
#define OFF_BHI  (2 * A_TILE)
#define OFF_BLO  (2 * A_TILE + B_TILE)
#define STAGE_B  (2 * A_TILE + 2 * B_TILE)   // 51200
#define SMEM_B   (2 * STAGE_B)               // 102400, double buffered

// Scratch (no allocation allowed -> __device__ globals).
// CRITICAL: referenced ONLY inside device code. Passing a __device__ global as
// a kernel argument from host code passes the HOST shadow symbol's address;
// on GB300 (HMM/ATS) that address is GPU-dereferenceable, so kernels silently
// read zero-filled host .bss -- the R6-R10 failure mode.
__device__ __align__(128) __nv_bfloat16 g_ahi[M_ * H_];
__device__ __align__(128) __nv_bfloat16 g_alo[M_ * H_];
__device__ __align__(128) __nv_bfloat16 g_xhi[M_ * H_];
__device__ __align__(128) __nv_bfloat16 g_xlo[M_ * H_];
__device__ __align__(128) __nv_bfloat16 g_w1hi[H_ * H_];
__device__ __align__(128) __nv_bfloat16 g_w1lo[H_ * H_];
__device__ __align__(128) __nv_bfloat16 g_w2hi[H_ * H_];
__device__ __align__(128) __nv_bfloat16 g_w2lo[H_ * H_];
__device__ __align__(128) float g_dotp[8 * M_];   // per-(nblk,warp-half) head partials

// ---------------------------------------------------------------------------
// Helpers
// ---------------------------------------------------------------------------
__device__ __forceinline__ void cp16(uint32_t smem, const void* gmem)
{
    asm volatile("cp.async.cg.shared.global [%0], [%1], 16;\n"
                 :: "r"(smem), "l"(gmem) : "memory");
}

__device__ __forceinline__ void ldsm_x4(uint32_t* r, uint32_t addr)
{
    asm volatile("ldmatrix.sync.aligned.m8n8.x4.shared.b16 {%0,%1,%2,%3}, [%4];"
                 : "=r"(r[0]), "=r"(r[1]), "=r"(r[2]), "=r"(r[3]) : "r"(addr));
}

__device__ __forceinline__ void mma_bf16(float* d, const uint32_t* a,
                                         uint32_t b0, uint32_t b1)
{
    asm volatile(
        "mma.sync.aligned.m16n8k16.row.col.f32.bf16.bf16.f32 "
        "{%0,%1,%2,%3}, {%4,%5,%6,%7}, {%8,%9}, {%0,%1,%2,%3};"
        : "+f"(d[0]), "+f"(d[1]), "+f"(d[2]), "+f"(d[3])
        : "r"(a[0]), "r"(a[1]), "r"(a[2]), "r"(a[3]), "r"(b0), "r"(b1));
}

__device__ __forceinline__ float gelu_exact(float x)
{
    return 0.5f * x * (1.0f + erff(x * 0.70710678118654752f));
}

__device__ __forceinline__ void split_bf16(float v, __nv_bfloat16& h, __nv_bfloat16& l)
{
    h = __float2bfloat16(v);
    l = __float2bfloat16(v - __bfloat162float(h));
}

// ---------------------------------------------------------------------------
// Kernel 1: per-(batch, statement) mean pooling -> split bf16 (g_ahi/g_alo).
// Sorted ids -> contiguous token range via binary search. One block per (b,s).
// ---------------------------------------------------------------------------
__global__ __launch_bounds__(256) void pool_kernel(const float* __restrict__ hidden,
                                                   const int*   __restrict__ sids)
{
    const int bs = blockIdx.x;
    const int b  = bs >> 7;
    const int s  = bs & (S_ - 1);

    __shared__ int s_lo, s_hi;
    if (threadIdx.x == 0) {
        const int* ids = sids + b * T_;
        int lo = 0, hi = T_;
        while (lo < hi) { int m = (lo + hi) >> 1; if (ids[m] < s) lo = m + 1; else hi = m; }
        s_lo = lo;
        hi = T_;
        while (lo < hi) { int m = (lo + hi) >> 1; if (ids[m] < s + 1) lo = m + 1; else hi = m; }
        s_hi = lo;
    }
    __syncthreads();

    const int lo  = s_lo;
    const int cnt = s_hi - s_lo;
    const float inv = 1.0f / (float)max(cnt, 1);

    const int c = threadIdx.x;
    float a0 = 0.f, a1 = 0.f, a2 = 0.f;
    const float* row = hidden + ((size_t)b * T_ + lo) * H_;
    for (int t = 0; t < cnt; ++t, row += H_) {
        a0 += row[c];
        a1 += row[c + 256];
        a2 += row[c + 512];
    }
    const size_t o = (size_t)bs * H_;
    __nv_bfloat16 h, l;
    split_bf16(a0 * inv, h, l); g_ahi[o + c]       = h; g_alo[o + c]       = l;
    split_bf16(a1 * inv, h, l); g_ahi[o + c + 256] = h; g_alo[o + c + 256] = l;
    split_bf16(a2 * inv, h, l); g_ahi[o + c + 512] = h; g_alo[o + c + 512] = l;
}

// ---------------------------------------------------------------------------
// Kernel 2: weight transpose + bf16 split.  W[k][n] -> hi/lo[n][k].
// which==0 -> g_w1hi/g_w1lo, which==1 -> g_w2hi/g_w2lo (selected in device code).
// ---------------------------------------------------------------------------
__global__ __launch_bounds__(256) void wsplit_kernel(const float* __restrict__ W,
                                                     int which)
{
    __nv_bfloat16* hi = which ? g_w2hi : g_w1hi;
    __nv_bfloat16* lo = which ? g_w2lo : g_w1lo;

    __shared__ float tile[32][33];
    const int kb = blockIdx.y * 32, nb = blockIdx.x * 32;
    const int tx = threadIdx.x, ty = threadIdx.y;   // 32 x 8

#pragma unroll
    for (int i = ty; i < 32; i += 8)
        tile[i][tx] = W[(size_t)(kb + i) * H_ + nb + tx];
    __syncthreads();
#pragma unroll
    for (int i = ty; i < 32; i += 8) {
        const float v = tile[tx][i];               // W[kb+tx][nb+i]
        const size_t o = (size_t)(nb + i) * H_ + kb + tx;
        __nv_bfloat16 h, l;
        split_bf16(v, h, l);
        hi[o] = h;
        lo[o] = l;
    }
}

// ---------------------------------------------------------------------------
// Kernel 3: fused split-bf16 mma.sync GEMM + bias + exact GELU.
// Per K-chunk, all three products on once-loaded tiles:
//   acc += Ahi.Bhi + Alo.Bhi + Ahi.Blo      (drops only Alo.Blo ~2^-16 rel)
// mma order sweeps all 4 live accumulators per product before revisiting one
// (chain distance 4) to cut HMMA RAW stalls.
// CTA 128x192, 8 warps of 32x96, BKC=32, cp.async double buffer, single wave.
// MODE 0: A=g_ahi/g_alo, B=g_w1*, out split bf16 -> g_xhi/g_xlo.
// MODE 1: A=g_xhi/g_xlo, B=g_w2*, fused head: gelu -> dot w3 -> g_dotp.
// ---------------------------------------------------------------------------
template <int MODE>
__global__ __launch_bounds__(256, 2) void gemm_mma_kernel(const float* __restrict__ bias,
                                                          const float* __restrict__ w3)
{
    const __nv_bfloat16* __restrict__ Ahi = MODE ? g_xhi : g_ahi;
    const __nv_bfloat16* __restrict__ Alo = MODE ? g_xlo : g_alo;
    const __nv_bfloat16* __restrict__ Bhi = MODE ? g_w2hi : g_w1hi;
    const __nv_bfloat16* __restrict__ Blo = MODE ? g_w2lo : g_w1lo;

    extern __shared__ __align__(16) char smem[];
    const uint32_t sb = (uint32_t)__cvta_generic_to_shared(smem);

    const int tid  = threadIdx.x;
    const int wid  = tid >> 5;
    const int lane = tid & 31;
    const int gid  = lane >> 2;        // groupID           (PTX fragment formulas)
    const int tig  = lane & 3;         // threadID_in_group
    const int m0 = blockIdx.y * BM;
    const int n0 = blockIdx.x * BN;

    // loader: A 1024 chunks of 16B (hi+lo), B 1536 chunks (hi+lo); 10/thread.
    auto issue = [&](int c, int buf) {
        const int kk = c * BKC;
        const uint32_t base = sb + buf * STAGE_B;
#pragma unroll
        for (int i = 0; i < 4; ++i) {                // A: 2 tiles x 128 rows x 4
            const int idx  = tid + i * 256;          // 0..1023
            const int tile = idx >> 9;               // 0=hi, 1=lo
            const int r    = (idx >> 2) & 127;
            const int cc   = idx & 3;
            const __nv_bfloat16* src = (tile ? Alo : Ahi)
                                     + (size_t)(m0 + r) * H_ + kk + cc * 8;
            cp16(base + tile * A_TILE + (uint32_t)(r * ROWB + cc * 16), src);
        }
#pragma unroll
        for (int i = 0; i < 6; ++i) {                // B: 2 tiles x 192 rows x 4
            const int idx  = tid + i * 256;          // 0..1535
            const int tile = idx / 768;              // 0=hi, 1=lo
            const int rr   = idx - tile * 768;
            const int r    = rr >> 2;
            const int cc   = rr & 3;
            const __nv_bfloat16* src = (tile ? Blo : Bhi)
                                     + (size_t)(n0 + r) * H_ + kk + cc * 8;
            cp16(base + OFF_BHI + tile * B_TILE + (uint32_t)(r * ROWB + cc * 16), src);
        }
        asm volatile("cp.async.commit_group;" ::: "memory");
    };

    // warp tile: 32 (m) x 96 (n);  8 warps = 4m x 2n
    const int wm = (wid & 3) * 32;
    const int wn = (wid >> 2) * 96;

    // ldmatrix.x4 lane addressing (audited): lanes 0-15 -> rows 0-15 at byte 0;
    // lanes 16-31 -> rows 0-15 at byte 16.
    const int lm_row = lane & 15;
    const int lm_col = (lane >> 4) * 16;

    float acc[2][12][4];
#pragma unroll
    for (int i = 0; i < 2; ++i)
#pragma unroll
        for (int j = 0; j < 12; ++j)
#pragma unroll
            for (int k = 0; k < 4; ++k) acc[i][j][k] = 0.f;

    issue(0, 0);
    issue(1, 1);

    for (int c = 0; c < NCH; ++c) {
        const int buf = c & 1;
        if (c + 1 < NCH) asm volatile("cp.async.wait_group 1;" ::: "memory");
        else             asm volatile("cp.async.wait_group 0;" ::: "memory");
        __syncthreads();

        const uint32_t st = sb + buf * STAGE_B;
        const uint32_t a_row = (uint32_t)((wm + lm_row) * ROWB) + lm_col;
        const uint32_t b_row = (uint32_t)((wn + lm_row) * ROWB) + lm_col;

#pragma unroll
        for (int kk2 = 0; kk2 < 2; ++kk2) {
            const uint32_t kb = kk2 * 32;           // byte offset of k16 half
            uint32_t ahi[2][4], alo[2][4];
            ldsm_x4(ahi[0], st + OFF_AHI + a_row + kb);
            ldsm_x4(ahi[1], st + OFF_AHI + a_row + 16 * ROWB + kb);
            ldsm_x4(alo[0], st + OFF_ALO + a_row + kb);
            ldsm_x4(alo[1], st + OFF_ALO + a_row + 16 * ROWB + kb);
#pragma unroll
            for (int g = 0; g < 6; ++g) {           // n-groups of 16
                uint32_t bh[4], bl[4];
                // regs: m0:(n0-7,k0-7) m1:(n8-15,k0-7) m2:(n0-7,k8-15) m3:(n8-15,k8-15)
                ldsm_x4(bh, st + OFF_BHI + b_row + (uint32_t)(g * 16 * ROWB) + kb);
                ldsm_x4(bl, st + OFF_BLO + b_row + (uint32_t)(g * 16 * ROWB) + kb);
                // product-major order: all 4 live accs per product before
                // revisiting one -> RAW chain distance 4 instead of 2.
                mma_bf16(acc[0][2 * g],     ahi[0], bh[0], bh[2]);
                mma_bf16(acc[0][2 * g + 1], ahi[0], bh[1], bh[3]);
                mma_bf16(acc[1][2 * g],     ahi[1], bh[0], bh[2]);
                mma_bf16(acc[1][2 * g + 1], ahi[1], bh[1], bh[3]);

                mma_bf16(acc[0][2 * g],     alo[0], bh[0], bh[2]);
                mma_bf16(acc[0][2 * g + 1], alo[0], bh[1], bh[3]);
                mma_bf16(acc[1][2 * g],     alo[1], bh[0], bh[2]);
                mma_bf16(acc[1][2 * g + 1], alo[1], bh[1], bh[3]);

                mma_bf16(acc[0][2 * g],     ahi[0], bl[0], bl[2]);
                mma_bf16(acc[0][2 * g + 1], ahi[0], bl[1], bl[3]);
                mma_bf16(acc[1][2 * g],     ahi[1], bl[0], bl[2]);
                mma_bf16(acc[1][2 * g + 1], ahi[1], bl[1], bl[3]);
            }
        }
        __syncthreads();
        if (c + 2 < NCH) issue(c + 2, buf);
    }

    // Epilogue: PTX C layout: c0/c1 at (gid, tig*2 /+1), c2/c3 at (gid+8, ...)
#pragma unroll
    for (int mt = 0; mt < 2; ++mt) {
        const int r0 = m0 + wm + mt * 16 + gid;
        float d0 = 0.f, d1 = 0.f;       // MODE 1: head partial dots (rows r0, r0+8)
#pragma unroll
        for (int nt = 0; nt < 12; ++nt) {
            const int col = n0 + wn + nt * 8 + tig * 2;
            const float bz0 = __ldg(&bias[col]);
            const float bz1 = __ldg(&bias[col + 1]);
            const float* a4 = acc[mt][nt];
            const float v00 = gelu_exact(a4[0] + bz0);
            const float v01 = gelu_exact(a4[1] + bz1);
            const float v10 = gelu_exact(a4[2] + bz0);
            const float v11 = gelu_exact(a4[3] + bz1);
            if (MODE == 0) {
                __nv_bfloat162 h0, l0, h1, l1;
                split_bf16(v00, h0.x, l0.x); split_bf16(v01, h0.y, l0.y);
                split_bf16(v10, h1.x, l1.x); split_bf16(v11, h1.y, l1.y);
                *(__nv_bfloat162*)(g_xhi + (size_t)r0 * H_ + col)       = h0;
                *(__nv_bfloat162*)(g_xlo + (size_t)r0 * H_ + col)       = l0;
                *(__nv_bfloat162*)(g_xhi + (size_t)(r0 + 8) * H_ + col) = h1;
                *(__nv_bfloat162*)(g_xlo + (size_t)(r0 + 8) * H_ + col) = l1;
            } else {
                const float w0 = __ldg(&w3[col]);
                const float w1 = __ldg(&w3[col + 1]);
                d0 += v00 * w0 + v01 * w1;
                d1 += v10 * w0 + v11 * w1;
            }
        }
        if (MODE == 1) {
            // reduce across the quad (tig 0..3 share the same rows)
            d0 += __shfl_xor_sync(0xffffffffu, d0, 1);
            d0 += __shfl_xor_sync(0xffffffffu, d0, 2);
            d1 += __shfl_xor_sync(0xffffffffu, d1, 1);
            d1 += __shfl_xor_sync(0xffffffffu, d1, 2);
            if (tig == 0) {
                const int p = blockIdx.x * 2 + (wid >> 2);   // 0..7, unique rows within p
                g_dotp[p * M_ + r0]     = d0;
                g_dotp[p * M_ + r0 + 8] = d1;
            }
        }
    }
}

// ---------------------------------------------------------------------------
// Kernel 4: out[i] = sigmoid(sum_p dotp[p][i] + b3).  8 deterministic partials.
// ---------------------------------------------------------------------------
__global__ __launch_bounds__(256) void finalize_kernel(const float* __restrict__ b3,
                                                       float* __restrict__ out)
{
    const int i = blockIdx.x * 256 + threadIdx.x;
    float s = b3[0];
#pragma unroll
    for (int p = 0; p < 8; ++p) s += g_dotp[p * M_ + i];
    out[i] = 1.0f / (1.0f + expf(-s));
}

// ---------------------------------------------------------------------------
// Launch: wsplit(w1,w2) -> pool -> gemm<0> -> gemm<1> (fused head) -> finalize.
// Only harness-provided d_in/d_out pointers cross the host->kernel boundary;
// all scratch is device-side symbols. Graph-capturable, allocation-free.
// ---------------------------------------------------------------------------
extern "C" void kernel_launch(void* const* d_in, const int* in_sizes, int n_in,
                              void* d_out, int out_size)
{
    const float* hidden = (const float*)d_in[0];
    const int*   sids   = (const int*)  d_in[1];
    const float* w1     = (const float*)d_in[2];
    const float* b1     = (const float*)d_in[3];
    const float* w2     = (const float*)d_in[4];
    const float* b2     = (const float*)d_in[5];
    const float* w3     = (const float*)d_in[6];
    const float* b3     = (const float*)d_in[7];
    float*       out    = (float*)d_out;

    cudaFuncSetAttribute(gemm_mma_kernel<0>,
                         cudaFuncAttributeMaxDynamicSharedMemorySize, SMEM_B);
    cudaFuncSetAttribute(gemm_mma_kernel<1>,
                         cudaFuncAttributeMaxDynamicSharedMemorySize, SMEM_B);

    dim3 wgrid(H_ / 32, H_ / 32);     // (24, 24)
    dim3 wblk(32, 8);
    wsplit_kernel<<<wgrid, wblk>>>(w1, 0);
    wsplit_kernel<<<wgrid, wblk>>>(w2, 1);

    pool_kernel<<<M_, 256>>>(hidden, sids);            // -> g_ahi / g_alo

    dim3 grid(H_ / BN, M_ / BM);                        // (4, 64) = 256 CTAs
    gemm_mma_kernel<0><<<grid, 256, SMEM_B>>>(b1, w3);  // -> g_xhi / g_xlo
    gemm_mma_kernel<1><<<grid, 256, SMEM_B>>>(b2, w3);  // -> g_dotp

    finalize_kernel<<<M_ / 256, 256>>>(b3, out);        // g_dotp -> out
}